// round 1
// baseline (speedup 1.0000x reference)
#include <cuda_runtime.h>

// Problem constants
#define BB   16384
#define S    17
#define V    29
#define D    128
#define NSEG 4
#define NL   6
#define EPS  1e-5f

// Tiling
#define BQ       4              // batches per CTA
#define ROWS     (BQ * S)       // 68
#define NTHREADS 256
#define NWARPS   8

// Shared memory layout (float offsets)
#define OFF_X   0                       // x tile        [68][128]
#define OFF_A   8704                    // scratch A     [68][128]
#define OFF_B   17408                   // scratch B     [68][128]
#define OFF_W   26112                   // weight stage  [128][128]
#define OFF_SC  42496                   // scores        [4][17][17]
#define OFF_M   43652                   // mask          [68]
#define OFF_SEG 43720                   // seg one-hot   [68][4]
#define SMEM_FLOATS 43992
#define SMEM_BYTES  (SMEM_FLOATS * 4)   // 175,968 B

// ---------------------------------------------------------------------------
// Stage a 128x128 fp32 weight matrix (row-major [k][n]) from global into smem.
__device__ __forceinline__ void load_w(const float* __restrict__ g,
                                       float* __restrict__ sw, int tid) {
    const float4* g4 = (const float4*)g;
    float4* s4 = (float4*)sw;
#pragma unroll
    for (int i = 0; i < (D * D / 4) / NTHREADS; ++i)
        s4[tid + i * NTHREADS] = g4[tid + i * NTHREADS];
}

// dst[r][n] = (relu?) src[r][:] . sw[:][n] + bias[n]   for all 68 rows.
// Each warp processes 4 rows at a time; each lane owns 4 output columns.
// Per k-iter: 1 LDS.128 (W) + 4 broadcast LDS.32 (x) feed 16 FFMA.
template <bool RELU>
__device__ __forceinline__ void gemm_rows(const float* __restrict__ src,
                                          const float* __restrict__ sw,
                                          const float* __restrict__ bias,
                                          float* __restrict__ dst,
                                          int warp, int lane) {
    const int c = lane * 4;
    const float4 bv = *(const float4*)&bias[c];
    for (int q = warp; q < ROWS / 4; q += NWARPS) {
        const float* x0 = src + (4 * q + 0) * D;
        const float* x1 = src + (4 * q + 1) * D;
        const float* x2 = src + (4 * q + 2) * D;
        const float* x3 = src + (4 * q + 3) * D;
        float4 a0 = bv, a1 = bv, a2 = bv, a3 = bv;
#pragma unroll 8
        for (int k = 0; k < D; ++k) {
            const float4 w = *(const float4*)&sw[k * D + c];
            const float v0 = x0[k], v1 = x1[k], v2 = x2[k], v3 = x3[k];
            a0.x += v0 * w.x; a0.y += v0 * w.y; a0.z += v0 * w.z; a0.w += v0 * w.w;
            a1.x += v1 * w.x; a1.y += v1 * w.y; a1.z += v1 * w.z; a1.w += v1 * w.w;
            a2.x += v2 * w.x; a2.y += v2 * w.y; a2.z += v2 * w.z; a2.w += v2 * w.w;
            a3.x += v3 * w.x; a3.y += v3 * w.y; a3.z += v3 * w.z; a3.w += v3 * w.w;
        }
        if (RELU) {
            a0.x = fmaxf(a0.x, 0.f); a0.y = fmaxf(a0.y, 0.f); a0.z = fmaxf(a0.z, 0.f); a0.w = fmaxf(a0.w, 0.f);
            a1.x = fmaxf(a1.x, 0.f); a1.y = fmaxf(a1.y, 0.f); a1.z = fmaxf(a1.z, 0.f); a1.w = fmaxf(a1.w, 0.f);
            a2.x = fmaxf(a2.x, 0.f); a2.y = fmaxf(a2.y, 0.f); a2.z = fmaxf(a2.z, 0.f); a2.w = fmaxf(a2.w, 0.f);
            a3.x = fmaxf(a3.x, 0.f); a3.y = fmaxf(a3.y, 0.f); a3.z = fmaxf(a3.z, 0.f); a3.w = fmaxf(a3.w, 0.f);
        }
        *(float4*)&dst[(4 * q + 0) * D + c] = a0;
        *(float4*)&dst[(4 * q + 1) * D + c] = a1;
        *(float4*)&dst[(4 * q + 2) * D + c] = a2;
        *(float4*)&dst[(4 * q + 3) * D + c] = a3;
    }
}

// x[r] = LN(x[r] + add[r]) * g + b   (warp per row)
__device__ __forceinline__ void ln_add(float* __restrict__ sx,
                                       const float* __restrict__ add,
                                       const float* __restrict__ g,
                                       const float* __restrict__ b,
                                       int warp, int lane) {
    const int c = lane * 4;
    const float4 gv = *(const float4*)&g[c];
    const float4 bv = *(const float4*)&b[c];
    for (int r = warp; r < ROWS; r += NWARPS) {
        const float4 xv = *(const float4*)&sx[r * D + c];
        const float4 av = *(const float4*)&add[r * D + c];
        float4 t;
        t.x = xv.x + av.x; t.y = xv.y + av.y; t.z = xv.z + av.z; t.w = xv.w + av.w;
        float s  = t.x + t.y + t.z + t.w;
        float sq = t.x * t.x + t.y * t.y + t.z * t.z + t.w * t.w;
#pragma unroll
        for (int o = 16; o; o >>= 1) {
            s  += __shfl_xor_sync(0xFFFFFFFFu, s,  o);
            sq += __shfl_xor_sync(0xFFFFFFFFu, sq, o);
        }
        const float mu  = s * (1.0f / D);
        const float var = sq * (1.0f / D) - mu * mu;
        const float inv = rsqrtf(var + EPS);
        float4 o4;
        o4.x = (t.x - mu) * inv * gv.x + bv.x;
        o4.y = (t.y - mu) * inv * gv.y + bv.y;
        o4.z = (t.z - mu) * inv * gv.z + bv.z;
        o4.w = (t.w - mu) * inv * gv.w + bv.w;
        *(float4*)&sx[r * D + c] = o4;
    }
}

// ---------------------------------------------------------------------------
__global__ __launch_bounds__(NTHREADS, 1)
void artistbert_kernel(const float* __restrict__ X,    const float* __restrict__ mask_in,
                       const float* __restrict__ seg_in,
                       const float* __restrict__ We,   const float* __restrict__ be,
                       const float* __restrict__ Wp,   const float* __restrict__ bp,
                       const float* __restrict__ Wsg,  const float* __restrict__ bsg,
                       const float* __restrict__ g1,   const float* __restrict__ b1,
                       const float* __restrict__ Wq,   const float* __restrict__ bq,
                       const float* __restrict__ Wk,   const float* __restrict__ bk,
                       const float* __restrict__ Wv,   const float* __restrict__ bv,
                       const float* __restrict__ g2,   const float* __restrict__ b2,
                       const float* __restrict__ Wd,   const float* __restrict__ bd,
                       const float* __restrict__ Wo,   const float* __restrict__ bo,
                       float* __restrict__ out) {
    extern __shared__ float sm[];
    float* sx    = sm + OFF_X;
    float* sa    = sm + OFF_A;
    float* sb    = sm + OFF_B;
    float* sw    = sm + OFF_W;
    float* ss    = sm + OFF_SC;
    float* smask = sm + OFF_M;
    float* sseg  = sm + OFF_SEG;

    const int tid  = threadIdx.x;
    const int warp = tid >> 5;
    const int lane = tid & 31;
    const int  b0       = blockIdx.x * BQ;
    const long base_row = (long)b0 * S;

    // ---- stage embedding tables + per-tile inputs ----
    for (int i = tid; i < V * D; i += NTHREADS) sw[i] = We[i];
    for (int i = tid; i < S * D; i += NTHREADS) {
        const int d = i & (D - 1);
        sa[i] = Wp[i] + bp[d] + be[d] + bsg[d];   // combined positional + biases
    }
    for (int i = tid; i < NSEG * D; i += NTHREADS) sa[S * D + i] = Wsg[i];
    {
        const float* Xb = X + base_row * V;
        for (int i = tid; i < ROWS * V; i += NTHREADS) sb[i] = Xb[i];
    }
    for (int i = tid; i < ROWS; i += NTHREADS) smask[i] = mask_in[base_row + i];
    {
        const float* Sg = seg_in + base_row * NSEG;
        for (int i = tid; i < ROWS * NSEG; i += NTHREADS) sseg[i] = Sg[i];
    }
    __syncthreads();

    // ---- embedding: sx = X@We + posc + seg@Wsg ----
    {
        const int c = lane * 4;
        for (int r = warp; r < ROWS; r += NWARPS) {
            const int s = r % S;
            float4 acc = *(const float4*)&sa[s * D + c];
#pragma unroll
            for (int j = 0; j < NSEG; ++j) {
                const float sv = sseg[r * NSEG + j];
                const float4 w = *(const float4*)&sa[S * D + j * D + c];
                acc.x += sv * w.x; acc.y += sv * w.y; acc.z += sv * w.z; acc.w += sv * w.w;
            }
            const float* xr = &sb[r * V];
#pragma unroll
            for (int v = 0; v < V; ++v) {
                const float xv = xr[v];
                const float4 w = *(const float4*)&sw[v * D + c];
                acc.x += xv * w.x; acc.y += xv * w.y; acc.z += xv * w.z; acc.w += xv * w.w;
            }
            *(float4*)&sx[r * D + c] = acc;
        }
    }
    __syncthreads();

    // ---- transformer layers ----
    for (int li = 0; li < NL; ++li) {
        // q = relu(x@Wq+bq) -> sa
        load_w(Wq + li * D * D, sw, tid); __syncthreads();
        gemm_rows<true>(sx, sw, bq + li * D, sa, warp, lane); __syncthreads();
        // k = relu(x@Wk+bk) -> sb
        load_w(Wk + li * D * D, sw, tid); __syncthreads();
        gemm_rows<true>(sx, sw, bk + li * D, sb, warp, lane); __syncthreads();

        // scores[b][qi][ki] = q.k (warp per dot)
        for (int idx = warp; idx < BQ * S * S; idx += NWARPS) {
            const int b   = idx / (S * S);
            const int rem = idx - b * S * S;
            const int qi  = rem / S;
            const int ki  = rem - qi * S;
            const float4 qv = *(const float4*)&sa[(b * S + qi) * D + lane * 4];
            const float4 kv = *(const float4*)&sb[(b * S + ki) * D + lane * 4];
            float p = qv.x * kv.x + qv.y * kv.y + qv.z * kv.z + qv.w * kv.w;
#pragma unroll
            for (int o = 16; o; o >>= 1) p += __shfl_xor_sync(0xFFFFFFFFu, p, o);
            if (lane == 0) ss[idx] = p;
        }
        __syncthreads();

        // softmax over last dim (thread per (b,qi) row)
        if (tid < ROWS) {
            float* row = &ss[(tid / S) * S * S + (tid % S) * S];
            float mx = row[0];
#pragma unroll
            for (int j = 1; j < S; ++j) mx = fmaxf(mx, row[j]);
            float sum = 0.f;
#pragma unroll
            for (int j = 0; j < S; ++j) { const float e = __expf(row[j] - mx); row[j] = e; sum += e; }
            const float inv = 1.0f / sum;
#pragma unroll
            for (int j = 0; j < S; ++j) row[j] *= inv;
        }
        __syncthreads();

        // v = relu(x@Wv+bv) -> sa (q dead)
        load_w(Wv + li * D * D, sw, tid); __syncthreads();
        gemm_rows<true>(sx, sw, bv + li * D, sa, warp, lane); __syncthreads();

        // attn = (scores @ v) * mask -> sb (k dead)
        {
            const int c = lane * 4;
            for (int r = warp; r < ROWS; r += NWARPS) {
                const int b  = r / S;
                const int qi = r - b * S;
                const float* p  = &ss[b * S * S + qi * S];
                const float* vb = &sa[(b * S) * D];
                float4 acc = make_float4(0.f, 0.f, 0.f, 0.f);
#pragma unroll
                for (int ki = 0; ki < S; ++ki) {
                    const float pv = p[ki];
                    const float4 v = *(const float4*)&vb[ki * D + c];
                    acc.x += pv * v.x; acc.y += pv * v.y; acc.z += pv * v.z; acc.w += pv * v.w;
                }
                const float m = smask[r];
                acc.x *= m; acc.y *= m; acc.z *= m; acc.w *= m;
                *(float4*)&sb[r * D + c] = acc;
            }
        }
        __syncthreads();

        // x = LN(x + attn)
        ln_add(sx, sb, g1 + li * D, b1 + li * D, warp, lane);
        __syncthreads();

        // d = x@Wd + bd -> sa (no relu)
        load_w(Wd + li * D * D, sw, tid); __syncthreads();
        gemm_rows<false>(sx, sw, bd + li * D, sa, warp, lane); __syncthreads();

        // x = LN(x + d)
        ln_add(sx, sa, g2 + li * D, b2 + li * D, warp, lane);
        __syncthreads();
    }

    // ---- output projection: out = x@Wo + bo ----
    for (int i = tid; i < D * 32; i += NTHREADS) {
        const int k = i >> 5, n = i & 31;
        sw[i] = (n < V) ? Wo[k * V + n] : 0.f;
    }
    __syncthreads();
    for (int r = warp; r < ROWS; r += NWARPS) {
        if (lane < V) {
            float acc = bo[lane];
            const float* xr = &sx[r * D];
#pragma unroll 8
            for (int k = 0; k < D; ++k) acc += xr[k] * sw[k * 32 + lane];
            out[(base_row + r) * V + lane] = acc;
        }
    }
}

// ---------------------------------------------------------------------------
extern "C" void kernel_launch(void* const* d_in, const int* in_sizes, int n_in,
                              void* d_out, int out_size) {
    (void)in_sizes; (void)n_in; (void)out_size;
    const float* X    = (const float*)d_in[0];
    const float* mask = (const float*)d_in[1];
    const float* seg  = (const float*)d_in[2];
    const float* We   = (const float*)d_in[3];
    const float* be   = (const float*)d_in[4];
    const float* Wp   = (const float*)d_in[5];
    const float* bp   = (const float*)d_in[6];
    const float* Wsg  = (const float*)d_in[7];
    const float* bsg  = (const float*)d_in[8];
    const float* g1   = (const float*)d_in[9];
    const float* b1   = (const float*)d_in[10];
    const float* Wq   = (const float*)d_in[11];
    const float* bq   = (const float*)d_in[12];
    const float* Wk   = (const float*)d_in[13];
    const float* bk   = (const float*)d_in[14];
    const float* Wv   = (const float*)d_in[15];
    const float* bv   = (const float*)d_in[16];
    const float* g2   = (const float*)d_in[17];
    const float* b2   = (const float*)d_in[18];
    const float* Wd   = (const float*)d_in[19];
    const float* bd   = (const float*)d_in[20];
    const float* Wo   = (const float*)d_in[21];
    const float* bo   = (const float*)d_in[22];
    float* out = (float*)d_out;

    cudaFuncSetAttribute(artistbert_kernel,
                         cudaFuncAttributeMaxDynamicSharedMemorySize, SMEM_BYTES);

    artistbert_kernel<<<BB / BQ, NTHREADS, SMEM_BYTES>>>(
        X, mask, seg, We, be, Wp, bp, Wsg, bsg, g1, b1,
        Wq, bq, Wk, bk, Wv, bv, g2, b2, Wd, bd, Wo, bo, out);
}

// round 4
// speedup vs baseline: 1.2216x; 1.2216x over previous
#include <cuda_runtime.h>

// Problem constants
#define BB   16384
#define S    17
#define V    29
#define D    128
#define NSEG 4
#define NL   6
#define EPS  1e-5f

// Tiling
#define BQ       4              // batches per CTA
#define ROWS     (BQ * S)       // 68
#define NTHREADS 544            // 17 warps: 68 rows / 4 rows-per-warp exactly
#define NWARPS   17

// Shared memory layout (float offsets)
#define OFF_X   0                       // x tile        [68][128]
#define OFF_A   8704                    // scratch A     [68][128]
#define OFF_B   17408                   // scratch B     [68][128]
#define OFF_W   26112                   // weight stage  [128][128]
#define OFF_SC  42496                   // scores        [4][17][17]
#define OFF_M   43652                   // mask          [68]
#define OFF_SEG 43720                   // seg one-hot   [68][4]
#define SMEM_FLOATS 43992
#define SMEM_BYTES  (SMEM_FLOATS * 4)   // 175,968 B

// ---------------------------------------------------------------------------
// Stage a 128x128 fp32 weight matrix (row-major [k][n]) from global into smem.
__device__ __forceinline__ void load_w(const float* __restrict__ g,
                                       float* __restrict__ sw, int tid) {
    const float4* g4 = (const float4*)g;
    float4* s4 = (float4*)sw;
    for (int i = tid; i < D * D / 4; i += NTHREADS)
        s4[i] = g4[i];
}

// NOTE: macro params use reserved-looking names so member accesses (.x/.y/.z/.w)
// cannot collide with an argument identifier.
#define FMA4(_acc_, _s_, _w_)                                                  \
    _acc_.x += (_s_) * (_w_).x; _acc_.y += (_s_) * (_w_).y;                    \
    _acc_.z += (_s_) * (_w_).z; _acc_.w += (_s_) * (_w_).w;

// dst[r][n] = (relu?) src[r][:] . sw[:][n] + bias[n]   for all 68 rows.
// Warp w owns rows 4w..4w+3 (17 warps cover 68 rows in one pass).
// Per 4-k group per warp: 4 LDS.128 W (16 crossbar cyc) + 4 broadcast LDS.128 x
// (4 cyc) feed 64 FFMA (32 issue cyc) -> FMA-bound.
template <bool RELU>
__device__ __forceinline__ void gemm_rows(const float* __restrict__ src,
                                          const float* __restrict__ sw,
                                          const float* __restrict__ bias,
                                          float* __restrict__ dst,
                                          int warp, int lane) {
    const int c = lane * 4;
    const float4 bvec = *(const float4*)&bias[c];
    const float* x0 = src + (4 * warp + 0) * D;
    const float* x1 = src + (4 * warp + 1) * D;
    const float* x2 = src + (4 * warp + 2) * D;
    const float* x3 = src + (4 * warp + 3) * D;
    float4 a0 = bvec, a1 = bvec, a2 = bvec, a3 = bvec;
#pragma unroll 4
    for (int k0 = 0; k0 < D; k0 += 4) {
        const float4 v0 = *(const float4*)(x0 + k0);
        const float4 v1 = *(const float4*)(x1 + k0);
        const float4 v2 = *(const float4*)(x2 + k0);
        const float4 v3 = *(const float4*)(x3 + k0);
        {
            const float4 wv = *(const float4*)&sw[(k0 + 0) * D + c];
            FMA4(a0, v0.x, wv) FMA4(a1, v1.x, wv) FMA4(a2, v2.x, wv) FMA4(a3, v3.x, wv)
        }
        {
            const float4 wv = *(const float4*)&sw[(k0 + 1) * D + c];
            FMA4(a0, v0.y, wv) FMA4(a1, v1.y, wv) FMA4(a2, v2.y, wv) FMA4(a3, v3.y, wv)
        }
        {
            const float4 wv = *(const float4*)&sw[(k0 + 2) * D + c];
            FMA4(a0, v0.z, wv) FMA4(a1, v1.z, wv) FMA4(a2, v2.z, wv) FMA4(a3, v3.z, wv)
        }
        {
            const float4 wv = *(const float4*)&sw[(k0 + 3) * D + c];
            FMA4(a0, v0.w, wv) FMA4(a1, v1.w, wv) FMA4(a2, v2.w, wv) FMA4(a3, v3.w, wv)
        }
    }
    if (RELU) {
        a0.x = fmaxf(a0.x, 0.f); a0.y = fmaxf(a0.y, 0.f); a0.z = fmaxf(a0.z, 0.f); a0.w = fmaxf(a0.w, 0.f);
        a1.x = fmaxf(a1.x, 0.f); a1.y = fmaxf(a1.y, 0.f); a1.z = fmaxf(a1.z, 0.f); a1.w = fmaxf(a1.w, 0.f);
        a2.x = fmaxf(a2.x, 0.f); a2.y = fmaxf(a2.y, 0.f); a2.z = fmaxf(a2.z, 0.f); a2.w = fmaxf(a2.w, 0.f);
        a3.x = fmaxf(a3.x, 0.f); a3.y = fmaxf(a3.y, 0.f); a3.z = fmaxf(a3.z, 0.f); a3.w = fmaxf(a3.w, 0.f);
    }
    *(float4*)&dst[(4 * warp + 0) * D + c] = a0;
    *(float4*)&dst[(4 * warp + 1) * D + c] = a1;
    *(float4*)&dst[(4 * warp + 2) * D + c] = a2;
    *(float4*)&dst[(4 * warp + 3) * D + c] = a3;
}

// x[r] = LN(x[r] + add[r]) * g + b   (4 rows per warp)
__device__ __forceinline__ void ln_add(float* __restrict__ sx,
                                       const float* __restrict__ add,
                                       const float* __restrict__ g,
                                       const float* __restrict__ b,
                                       int warp, int lane) {
    const int c = lane * 4;
    const float4 gv = *(const float4*)&g[c];
    const float4 bvec = *(const float4*)&b[c];
    for (int r = warp; r < ROWS; r += NWARPS) {
        const float4 xv = *(const float4*)&sx[r * D + c];
        const float4 av = *(const float4*)&add[r * D + c];
        float4 t;
        t.x = xv.x + av.x; t.y = xv.y + av.y; t.z = xv.z + av.z; t.w = xv.w + av.w;
        float s  = t.x + t.y + t.z + t.w;
        float sq = t.x * t.x + t.y * t.y + t.z * t.z + t.w * t.w;
#pragma unroll
        for (int o = 16; o; o >>= 1) {
            s  += __shfl_xor_sync(0xFFFFFFFFu, s,  o);
            sq += __shfl_xor_sync(0xFFFFFFFFu, sq, o);
        }
        const float mu  = s * (1.0f / D);
        const float var = sq * (1.0f / D) - mu * mu;
        const float inv = rsqrtf(var + EPS);
        float4 o4;
        o4.x = (t.x - mu) * inv * gv.x + bvec.x;
        o4.y = (t.y - mu) * inv * gv.y + bvec.y;
        o4.z = (t.z - mu) * inv * gv.z + bvec.z;
        o4.w = (t.w - mu) * inv * gv.w + bvec.w;
        *(float4*)&sx[r * D + c] = o4;
    }
}

// ---------------------------------------------------------------------------
__global__ __launch_bounds__(NTHREADS, 1)
void artistbert_kernel(const float* __restrict__ X,    const float* __restrict__ mask_in,
                       const float* __restrict__ seg_in,
                       const float* __restrict__ We,   const float* __restrict__ be,
                       const float* __restrict__ Wp,   const float* __restrict__ bp,
                       const float* __restrict__ Wsg,  const float* __restrict__ bsg,
                       const float* __restrict__ g1,   const float* __restrict__ b1,
                       const float* __restrict__ Wq,   const float* __restrict__ bq,
                       const float* __restrict__ Wk,   const float* __restrict__ bk,
                       const float* __restrict__ Wv,   const float* __restrict__ bv,
                       const float* __restrict__ g2,   const float* __restrict__ b2,
                       const float* __restrict__ Wd,   const float* __restrict__ bd,
                       const float* __restrict__ Wo,   const float* __restrict__ bo,
                       float* __restrict__ out) {
    extern __shared__ float sm[];
    float* sx    = sm + OFF_X;
    float* sa    = sm + OFF_A;
    float* sb    = sm + OFF_B;
    float* sw    = sm + OFF_W;
    float* ss    = sm + OFF_SC;
    float* smask = sm + OFF_M;
    float* sseg  = sm + OFF_SEG;

    const int tid  = threadIdx.x;
    const int warp = tid >> 5;
    const int lane = tid & 31;
    const int  b0       = blockIdx.x * BQ;
    const long base_row = (long)b0 * S;

    // ---- stage embedding tables + per-tile inputs ----
    for (int i = tid; i < V * D; i += NTHREADS) sw[i] = We[i];
    for (int i = tid; i < S * D; i += NTHREADS) {
        const int d = i & (D - 1);
        sa[i] = Wp[i] + bp[d] + be[d] + bsg[d];   // combined positional + biases
    }
    for (int i = tid; i < NSEG * D; i += NTHREADS) sa[S * D + i] = Wsg[i];
    {
        const float* Xb = X + base_row * V;
        for (int i = tid; i < ROWS * V; i += NTHREADS) sb[i] = Xb[i];
    }
    for (int i = tid; i < ROWS; i += NTHREADS) smask[i] = mask_in[base_row + i];
    {
        const float* Sg = seg_in + base_row * NSEG;
        for (int i = tid; i < ROWS * NSEG; i += NTHREADS) sseg[i] = Sg[i];
    }
    __syncthreads();

    // ---- embedding: sx = X@We + posc + seg@Wsg ----
    {
        const int c = lane * 4;
        for (int r = warp; r < ROWS; r += NWARPS) {
            const int s = r % S;
            float4 acc = *(const float4*)&sa[s * D + c];
#pragma unroll
            for (int j = 0; j < NSEG; ++j) {
                const float sv = sseg[r * NSEG + j];
                const float4 wv = *(const float4*)&sa[S * D + j * D + c];
                FMA4(acc, sv, wv)
            }
            const float* xr = &sb[r * V];
#pragma unroll
            for (int vtok = 0; vtok < V; ++vtok) {
                const float xv = xr[vtok];
                const float4 wv = *(const float4*)&sw[vtok * D + c];
                FMA4(acc, xv, wv)
            }
            *(float4*)&sx[r * D + c] = acc;
        }
    }
    __syncthreads();

    // ---- transformer layers ----
    for (int li = 0; li < NL; ++li) {
        // q = relu(x@Wq+bq) -> sa
        load_w(Wq + li * D * D, sw, tid); __syncthreads();
        gemm_rows<true>(sx, sw, bq + li * D, sa, warp, lane); __syncthreads();
        // k = relu(x@Wk+bk) -> sb
        load_w(Wk + li * D * D, sw, tid); __syncthreads();
        gemm_rows<true>(sx, sw, bk + li * D, sb, warp, lane); __syncthreads();

        // scores[b][qi][ki] = q.k (warp per dot; 1156/17 = 68 per warp)
        for (int idx = warp; idx < BQ * S * S; idx += NWARPS) {
            const int b   = idx / (S * S);
            const int rem = idx - b * S * S;
            const int qi  = rem / S;
            const int ki  = rem - qi * S;
            const float4 qv = *(const float4*)&sa[(b * S + qi) * D + lane * 4];
            const float4 kv = *(const float4*)&sb[(b * S + ki) * D + lane * 4];
            float p = qv.x * kv.x + qv.y * kv.y + qv.z * kv.z + qv.w * kv.w;
#pragma unroll
            for (int o = 16; o; o >>= 1) p += __shfl_xor_sync(0xFFFFFFFFu, p, o);
            if (lane == 0) ss[idx] = p;
        }
        __syncthreads();

        // softmax over last dim (thread per (b,qi) row)
        if (tid < ROWS) {
            float* row = &ss[(tid / S) * S * S + (tid % S) * S];
            float mx = row[0];
#pragma unroll
            for (int j = 1; j < S; ++j) mx = fmaxf(mx, row[j]);
            float sum = 0.f;
#pragma unroll
            for (int j = 0; j < S; ++j) { const float e = __expf(row[j] - mx); row[j] = e; sum += e; }
            const float inv = 1.0f / sum;
#pragma unroll
            for (int j = 0; j < S; ++j) row[j] *= inv;
        }
        __syncthreads();

        // v = relu(x@Wv+bv) -> sa (q dead)
        load_w(Wv + li * D * D, sw, tid); __syncthreads();
        gemm_rows<true>(sx, sw, bv + li * D, sa, warp, lane); __syncthreads();

        // attn = (scores @ v) * mask -> sb (k dead)
        {
            const int c = lane * 4;
            for (int r = warp; r < ROWS; r += NWARPS) {
                const int b  = r / S;
                const int qi = r - b * S;
                const float* p  = &ss[b * S * S + qi * S];
                const float* vb = &sa[(b * S) * D];
                float4 acc = make_float4(0.f, 0.f, 0.f, 0.f);
#pragma unroll
                for (int ki = 0; ki < S; ++ki) {
                    const float pv = p[ki];
                    const float4 vv = *(const float4*)&vb[ki * D + c];
                    FMA4(acc, pv, vv)
                }
                const float m = smask[r];
                acc.x *= m; acc.y *= m; acc.z *= m; acc.w *= m;
                *(float4*)&sb[r * D + c] = acc;
            }
        }
        __syncthreads();

        // x = LN(x + attn)
        ln_add(sx, sb, g1 + li * D, b1 + li * D, warp, lane);
        __syncthreads();

        // d = x@Wd + bd -> sa (no relu)
        load_w(Wd + li * D * D, sw, tid); __syncthreads();
        gemm_rows<false>(sx, sw, bd + li * D, sa, warp, lane); __syncthreads();

        // x = LN(x + d)
        ln_add(sx, sa, g2 + li * D, b2 + li * D, warp, lane);
        __syncthreads();
    }

    // ---- output projection: out = x@Wo + bo ----
    for (int i = tid; i < D * 32; i += NTHREADS) {
        const int k = i >> 5, n = i & 31;
        sw[i] = (n < V) ? Wo[k * V + n] : 0.f;
    }
    __syncthreads();
    for (int r = warp; r < ROWS; r += NWARPS) {
        if (lane < V) {
            float acc = bo[lane];
            const float* xr = &sx[r * D];
#pragma unroll 8
            for (int k = 0; k < D; ++k) acc += xr[k] * sw[k * 32 + lane];
            out[(base_row + r) * V + lane] = acc;
        }
    }
}

// ---------------------------------------------------------------------------
extern "C" void kernel_launch(void* const* d_in, const int* in_sizes, int n_in,
                              void* d_out, int out_size) {
    (void)in_sizes; (void)n_in; (void)out_size;
    const float* X    = (const float*)d_in[0];
    const float* mask = (const float*)d_in[1];
    const float* seg  = (const float*)d_in[2];
    const float* We   = (const float*)d_in[3];
    const float* be   = (const float*)d_in[4];
    const float* Wp   = (const float*)d_in[5];
    const float* bp   = (const float*)d_in[6];
    const float* Wsg  = (const float*)d_in[7];
    const float* bsg  = (const float*)d_in[8];
    const float* g1   = (const float*)d_in[9];
    const float* b1   = (const float*)d_in[10];
    const float* Wq   = (const float*)d_in[11];
    const float* bq   = (const float*)d_in[12];
    const float* Wk   = (const float*)d_in[13];
    const float* bk   = (const float*)d_in[14];
    const float* Wv   = (const float*)d_in[15];
    const float* bv   = (const float*)d_in[16];
    const float* g2   = (const float*)d_in[17];
    const float* b2   = (const float*)d_in[18];
    const float* Wd   = (const float*)d_in[19];
    const float* bd   = (const float*)d_in[20];
    const float* Wo   = (const float*)d_in[21];
    const float* bo   = (const float*)d_in[22];
    float* out = (float*)d_out;

    cudaFuncSetAttribute(artistbert_kernel,
                         cudaFuncAttributeMaxDynamicSharedMemorySize, SMEM_BYTES);

    artistbert_kernel<<<BB / BQ, NTHREADS, SMEM_BYTES>>>(
        X, mask, seg, We, be, Wp, bp, Wsg, bsg, g1, b1,
        Wq, bq, Wk, bk, Wv, bv, g2, b2, Wd, bd, Wo, bo, out);
}